// round 4
// baseline (speedup 1.0000x reference)
#include <cuda_runtime.h>
#include <cuda_bf16.h>
#include <math.h>
#include <stdint.h>

#define NB    8
#define NEq   256
#define SSq   21
#define NSTEP 20
#define DDim  256
#define HHn   8
#define HDn   32
#define VVn   10000
#define TTn   1920
#define VPAD  10112   // 79*128
#define MTOT  (NSTEP*NEq)  // 5120

// ------------------------- device scratch -------------------------
__device__ __align__(16) float g_value [NB*HHn*TTn*HDn];
__device__ __align__(16) float g_mixp  [4*NEq*512];
__device__ __align__(16) float g_hq    [NEq*512];          // [h | query]
__device__ __align__(16) float g_xh    [NEq*1024];         // [emb | attn | query | h]
__device__ __align__(16) float g_hseq  [MTOT*DDim];        // h2 per step
__device__ __align__(16) float g_c     [NEq*DDim];
__device__ __align__(16) float g_bigb  [512];
__device__ __align__(16) __nv_bfloat16 g_bigwt  [512*512];     // mix weights [n][k]
__device__ __align__(16) __nv_bfloat16 g_gatewt [1024*1024];   // gate-interleaved [n=4d+gate][k]
__device__ __align__(16) __nv_bfloat16 g_logitwt[VPAD*256];    // [n][k]
__device__ __align__(16) __nv_bfloat16 g_ctxwt  [256*32];      // [n][k]
__device__ __align__(16) __nv_bfloat16 g_valuewt[256*256];     // [n][k]

__device__ __forceinline__ float tanha(float x) {
    float y; asm("tanh.approx.f32 %0, %1;" : "=f"(y) : "f"(x)); return y;
}
__device__ __forceinline__ void mma16816(float* c, const uint32_t* a, const uint32_t* b) {
    asm volatile(
        "mma.sync.aligned.m16n8k16.row.col.f32.bf16.bf16.f32 "
        "{%0,%1,%2,%3}, {%4,%5,%6,%7}, {%8,%9}, {%0,%1,%2,%3};"
        : "+f"(c[0]), "+f"(c[1]), "+f"(c[2]), "+f"(c[3])
        : "r"(a[0]), "r"(a[1]), "r"(a[2]), "r"(a[3]), "r"(b[0]), "r"(b[1]));
}
__device__ __forceinline__ void cpasync16(uint32_t dst, const void* src) {
    asm volatile("cp.async.cg.shared.global [%0], [%1], 16;" :: "r"(dst), "l"(src));
}

// ------------------------- unified bf16 tensor-core GEMM -------------------------
// Block tile 64(M) x 128(N), 8 warps (2x4), warp tile 32x32.
// A fp32 -> bf16 smem (256-wide k-chunks); B bf16 [N][K] via cp.async double buffer.
// MODE 0: C[z*partStride + m*N + n] = acc (+bias)      (mix split-K partials)
// MODE 1: value scatter: g_value[b][h][t][hd] = (acc+bias)*mask
// MODE 2: gates+LSTM fused epilogue (gate-interleaved cols)
// MODE 3: logits scatter to out[(q*NSTEP+st)*VVn + n] + bias
template<int MODE>
__global__ __launch_bounds__(256)
void gemm_mma(const float* __restrict__ A, int lda,
              const __nv_bfloat16* __restrict__ Wt, int ldw,
              const float* __restrict__ bias,
              float* __restrict__ C, int N,
              int kChunk, int partStride,
              const float* __restrict__ mask, int step)
{
    extern __shared__ char smem[];
    uint32_t* Asw = (uint32_t*)smem;                 // [64][132] words
    uint32_t* Bsw = (uint32_t*)(smem + 33792);       // [2][128][36] words
    const int SAW = 132;

    const int tid  = threadIdx.x;
    const int lane = tid & 31, warp = tid >> 5;
    const int wm = warp >> 2, wn = warp & 3;
    const int g = lane >> 2, t = lane & 3;
    const int n0   = blockIdx.x * 128;
    const int row0 = blockIdx.y * 64;
    const int kbeg = blockIdx.z * kChunk;
    const int nkT  = kChunk >> 4;

    const int bn = tid >> 1;
    const int bq = (tid & 1) << 3;
    const uint32_t bsm = (uint32_t)__cvta_generic_to_shared(Bsw);

    cpasync16(bsm + (uint32_t)((bn*36 + (bq>>1))*4),
              Wt + (size_t)(n0 + bn) * ldw + kbeg + bq);
    asm volatile("cp.async.commit_group;");

    float acc[2][4][4];
#pragma unroll
    for (int i = 0; i < 2; i++)
#pragma unroll
        for (int j = 0; j < 4; j++)
#pragma unroll
            for (int q = 0; q < 4; q++) acc[i][j][q] = 0.f;

    for (int ksg = 0; ksg < nkT; ksg++) {
        __syncthreads();                       // old readers done before A re-store
        if ((ksg & 15) == 0) {
            int kA = kbeg + ((ksg >> 4) << 8);
            int KC = kChunk - (kA - kbeg); if (KC > 256) KC = 256;
            int sh = (KC == 256) ? 8 : 7;
            for (int idx = tid * 4; idx < (64 << sh); idx += 1024) {
                int r = idx >> sh, cc = idx & (KC - 1);
                float4 v = *(const float4*)(A + (size_t)(row0 + r) * lda + kA + cc);
                __nv_bfloat162 p0 = __float22bfloat162_rn(make_float2(v.x, v.y));
                __nv_bfloat162 p1 = __float22bfloat162_rn(make_float2(v.z, v.w));
                Asw[r * SAW + (cc >> 1)]     = *(uint32_t*)&p0;
                Asw[r * SAW + (cc >> 1) + 1] = *(uint32_t*)&p1;
            }
        }
        if (ksg + 1 < nkT)
            cpasync16(bsm + (uint32_t)(((((ksg+1)&1)*128*36) + bn*36 + (bq>>1))*4),
                      Wt + (size_t)(n0 + bn) * ldw + kbeg + (ksg + 1) * 16 + bq);
        asm volatile("cp.async.commit_group;");
        asm volatile("cp.async.wait_group 1;");
        __syncthreads();

        const int wo = (ksg & 15) * 8;
        uint32_t a[2][4];
#pragma unroll
        for (int mt = 0; mt < 2; mt++) {
            const uint32_t* ap = Asw + (wm*32 + mt*16 + g) * SAW + wo + t;
            a[mt][0] = ap[0];
            a[mt][1] = ap[8 * SAW];
            a[mt][2] = ap[4];
            a[mt][3] = ap[8 * SAW + 4];
        }
        const uint32_t* bbase = Bsw + (ksg & 1) * 128 * 36;
        uint32_t bf[4][2];
#pragma unroll
        for (int nt = 0; nt < 4; nt++) {
            const uint32_t* bp = bbase + (wn*32 + nt*8 + g) * 36 + t;
            bf[nt][0] = bp[0];
            bf[nt][1] = bp[4];
        }
#pragma unroll
        for (int mt = 0; mt < 2; mt++)
#pragma unroll
            for (int nt = 0; nt < 4; nt++)
                mma16816(acc[mt][nt], a[mt], bf[nt]);
    }

    if (MODE == 0) {
        const size_t zb = (size_t)blockIdx.z * partStride;
#pragma unroll
        for (int mt = 0; mt < 2; mt++) {
            int m = row0 + wm*32 + mt*16 + g;
#pragma unroll
            for (int nt = 0; nt < 4; nt++) {
                int n = n0 + wn*32 + nt*8 + (t << 1);
                float* c = acc[mt][nt];
                *(float2*)(C + zb + (size_t)m * N + n)       = make_float2(c[0], c[1]);
                *(float2*)(C + zb + (size_t)(m + 8) * N + n) = make_float2(c[2], c[3]);
            }
        }
    } else if (MODE == 1) {
#pragma unroll
        for (int mt = 0; mt < 2; mt++) {
#pragma unroll
            for (int mi = 0; mi < 2; mi++) {
                int m  = row0 + wm*32 + mt*16 + g + mi*8;
                int b  = m / TTn;
                int tt = m - b * TTn;
                float mk = mask[m];
#pragma unroll
                for (int nt = 0; nt < 4; nt++) {
                    int n  = n0 + wn*32 + nt*8 + (t << 1);
                    int h  = n >> 5, hd = n & 31;
                    float* c = acc[mt][nt];
                    float v0 = (c[mi*2]   + bias[n])     * mk;
                    float v1 = (c[mi*2+1] + bias[n + 1]) * mk;
                    *(float2*)(g_value + (((size_t)(b*HHn + h))*TTn + tt)*HDn + hd)
                        = make_float2(v0, v1);
                }
            }
        }
    } else if (MODE == 2) {
        __syncthreads();
        float* sC = (float*)smem;   // [64][128]
#pragma unroll
        for (int mt = 0; mt < 2; mt++) {
            int lr = wm*32 + mt*16 + g;
#pragma unroll
            for (int nt = 0; nt < 4; nt++) {
                int lc = wn*32 + nt*8 + (t << 1);
                float* c = acc[mt][nt];
                sC[lr*128 + lc]     = c[0];  sC[lr*128 + lc + 1]     = c[1];
                sC[(lr+8)*128 + lc] = c[2];  sC[(lr+8)*128 + lc + 1] = c[3];
            }
        }
        __syncthreads();
        const int d0 = n0 >> 2;
        for (int i = tid; i < 2048; i += 256) {
            int mloc = i >> 5, dloc = i & 31;
            int m = row0 + mloc, d = d0 + dloc;
            const float* gr = sC + mloc*128 + dloc*4;
            float gi = gr[0], gf = gr[1], gg = gr[2], go = gr[3];
            float c  = g_c[m*DDim + d];
            float sf = 1.f / (1.f + expf(-gf));
            float si = 1.f / (1.f + expf(-gi));
            float so = 1.f / (1.f + expf(-go));
            float c2 = sf * c + si * tanhf(gg);
            float h2 = so * tanhf(c2);
            g_c[m*DDim + d]         = c2;
            g_hq[m*512 + d]         = h2;
            g_xh[m*1024 + 768 + d]  = h2;
            g_hseq[((size_t)step*NEq + m)*DDim + d] = h2;
        }
    } else { // MODE 3: logits -> out scatter
#pragma unroll
        for (int mt = 0; mt < 2; mt++) {
#pragma unroll
            for (int mi = 0; mi < 2; mi++) {
                int m  = row0 + wm*32 + mt*16 + g + mi*8;
                int q  = m & 255, st = m >> 8;
                float* orow = C + ((size_t)q * NSTEP + st) * VVn;
#pragma unroll
                for (int nt = 0; nt < 4; nt++) {
                    int n = n0 + wn*32 + nt*8 + (t << 1);
                    if (n < VVn) {
                        float* c = acc[mt][nt];
                        *(float2*)(orow + n) = make_float2(c[mi*2]   + bias[n],
                                                           c[mi*2+1] + bias[n+1]);
                    }
                }
            }
        }
    }
}

// ------------------------- preamble kernels -------------------------
__global__ void build_bigwt(const float* __restrict__ offw, const float* __restrict__ aww,
                            const float* __restrict__ hsw,  const float* __restrict__ offb,
                            const float* __restrict__ awb,  const float* __restrict__ hsb)
{
    int i = blockIdx.x * 256 + threadIdx.x;
    int n = i >> 9, k = i & 511;
    float v;
    if (n < 128)      v = offw[k*128 + n];
    else if (n < 256) v = aww[k*128 + (n - 128)];
    else              v = (k < 256) ? hsw[k*256 + (n - 256)] : 0.f;
    g_bigwt[i] = __float2bfloat16(v);
    if (i < 512)
        g_bigb[i] = (i < 128) ? offb[i] : (i < 256) ? awb[i-128] : hsb[i-256];
}

__global__ void build_gatewt(const float* __restrict__ wih, const float* __restrict__ whh)
{
    int i = blockIdx.x * 256 + threadIdx.x;      // 0 .. 1024*1024-1
    int n = i >> 10, k = i & 1023;
    int d = n >> 2, gate = n & 3;
    int j = gate * 256 + d;
    float v = (k < 768) ? wih[k*1024 + j] : whh[(k - 768)*1024 + j];
    g_gatewt[i] = __float2bfloat16(v);
}

__global__ void build_logitwt(const float* __restrict__ lw)
{
    int i = blockIdx.x * 256 + threadIdx.x;      // 0 .. VPAD*256-1
    int k = i / VPAD, n = i - k * VPAD;
    float v = (n < VVn) ? lw[(size_t)k * VVn + n] : 0.f;
    g_logitwt[(size_t)n * 256 + k] = __float2bfloat16(v);
}

__global__ void build_misc(const float* __restrict__ ctxw, const float* __restrict__ valuew)
{
    int i = blockIdx.x * 256 + threadIdx.x;      // 0 .. 65535
    if (i < 256*32) {
        int n = i >> 5, k = i & 31;
        g_ctxwt[n*32 + k] = __float2bfloat16(ctxw[k*256 + n]);
    }
    int n = i >> 8, k = i & 255;
    g_valuewt[n*256 + k] = __float2bfloat16(valuew[k*256 + n]);
}

__global__ void init_state(const float* __restrict__ query)
{
    int n = blockIdx.x, d = threadIdx.x;
    float q = query[n*DDim + d];
    g_c[n*DDim + d] = 0.f;
    g_hq[n*512 + d]        = 0.f;
    g_hq[n*512 + 256 + d]  = q;
    g_xh[n*1024 + 512 + d] = q;
    g_xh[n*1024 + 768 + d] = 0.f;
}

// ------------------------- fused MSDA (mma phase C) -------------------------
__global__ __launch_bounds__(256)
void msda_step(const float* __restrict__ rp,     const float* __restrict__ vr,
               const int*   __restrict__ seq,    const float* __restrict__ embw,
               const float* __restrict__ ctxb,   const float* __restrict__ alphaw,
               const float* __restrict__ alphab, int step)
{
    __shared__ uint32_t s_hsampb[128*17];   // bf16 [128][34] halves, row stride 17 words
    __shared__ uint32_t s_ctx[256*17];      // bf16 ctx_w^T [256][32], stride 17 words
    __shared__ float s_hb[256];
    __shared__ float s_aww[256];
    __shared__ float s_off[128];
    __shared__ float s_aw[128];
    __shared__ float s_alpha[128];
    __shared__ float s_wgt[128];

    const int n    = blockIdx.x;
    const int b    = n >> 5;
    const int tid  = threadIdx.x;
    const int lane = tid & 31;
    const int w    = tid >> 5;

    // ---- phase A ----
    {
        int tok = (step == 0) ? 1 : seq[n*SSq + step - 1];
        g_xh[n*1024 + tid] = embw[(size_t)tok * DDim + tid];
    }
    {
        float s = 0.f;
#pragma unroll
        for (int z = 0; z < 4; z++) s += g_mixp[z*(NEq*512) + n*512 + 256 + tid];
        s_hb[tid] = s + g_bigb[256 + tid] + ctxb[tid];
        s_aww[tid] = alphaw[tid];
    }
    {   // load ctx_w^T into smem (4096 words)
        const uint32_t* cg = (const uint32_t*)g_ctxwt;
        for (int i = tid; i < 256*16; i += 256)
            s_ctx[(i >> 4)*17 + (i & 15)] = cg[i];
    }
    if (tid < 128) {
        float so = 0.f, sa = 0.f;
#pragma unroll
        for (int z = 0; z < 4; z++) {
            so += g_mixp[z*(NEq*512) + n*512 + tid];
            sa += g_mixp[z*(NEq*512) + n*512 + 128 + tid];
        }
        so += g_bigb[tid];
        sa += g_bigb[128 + tid];
        s_off[tid] = so;
        float m = sa;
#pragma unroll
        for (int o = 8; o; o >>= 1) m = fmaxf(m, __shfl_xor_sync(0xffffffffu, m, o));
        float e = __expf(sa - m);
        float sm = e;
#pragma unroll
        for (int o = 8; o; o >>= 1) sm += __shfl_xor_sync(0xffffffffu, sm, o);
        s_aw[tid] = e / sm;
    }
    __syncthreads();

    // ---- phase B: bilinear sampling -> bf16 smem ----
    {
        const float rpn = rp[n];
        __nv_bfloat16* hs = (__nv_bfloat16*)s_hsampb;
#pragma unroll
        for (int i = 0; i < 16; i++) {
            int r = (w << 4) + i;
            int h = r >> 4;
            int l = (r >> 2) & 3;
            int shape_l = 1024 >> l;
            int start_l = 2048 - (2048 >> l);
            float refl = rpn * vr[b*4 + l];
            float x = refl * (float)shape_l + s_off[r] - 0.5f;
            float x0f = floorf(x);
            float wf = x - x0f;
            int x0 = (int)x0f;
            const float* vbase = g_value + (((size_t)(b*HHn + h))*TTn + start_l) * HDn;
            float g0 = (x0 >= 0     && x0     < shape_l) ? vbase[(size_t)x0     * HDn + lane] : 0.f;
            float g1 = (x0 + 1 >= 0 && x0 + 1 < shape_l) ? vbase[(size_t)(x0+1) * HDn + lane] : 0.f;
            hs[r*34 + lane] = __float2bfloat16((g0 * (1.f - wf) + g1 * wf) * s_aw[r]);
        }
    }
    __syncthreads();

    // ---- phase C: alpha via tensor cores ----
    {
        const int g = lane >> 2, t = lane & 3;
        const int r0 = w << 4;
        const float ab = alphab[0];

        uint32_t a[2][4];
#pragma unroll
        for (int ks = 0; ks < 2; ks++) {
            const uint32_t* ap = s_hsampb + (r0 + g) * 17 + ks*8 + t;
            a[ks][0] = ap[0];
            a[ks][1] = ap[8 * 17];
            a[ks][2] = ap[4];
            a[ks][3] = ap[8 * 17 + 4];
        }
        float p0 = 0.f, p1 = 0.f;
#pragma unroll
        for (int nb = 0; nb < 256; nb += 8) {
            float c[4] = {0.f, 0.f, 0.f, 0.f};
#pragma unroll
            for (int ks = 0; ks < 2; ks++) {
                const uint32_t* bp = s_ctx + (nb + g) * 17 + ks*8 + t;
                uint32_t bf2[2] = { bp[0], bp[4] };
                mma16816(c, a[ks], bf2);
            }
            int col = nb + (t << 1);
            float hb0 = s_hb[col], hb1 = s_hb[col + 1];
            float aw0 = s_aww[col], aw1 = s_aww[col + 1];
            p0 = fmaf(tanha(c[0] + hb0), aw0, fmaf(tanha(c[1] + hb1), aw1, p0));
            p1 = fmaf(tanha(c[2] + hb0), aw0, fmaf(tanha(c[3] + hb1), aw1, p1));
        }
        p0 += __shfl_xor_sync(0xffffffffu, p0, 1);
        p0 += __shfl_xor_sync(0xffffffffu, p0, 2);
        p1 += __shfl_xor_sync(0xffffffffu, p1, 1);
        p1 += __shfl_xor_sync(0xffffffffu, p1, 2);
        if (t == 0) {
            s_alpha[r0 + g]     = p0 + ab;
            s_alpha[r0 + g + 8] = p1 + ab;
        }
    }
    __syncthreads();

    // ---- phase D: softmax over 16 per head ----
    if (tid < 128) {
        float v = s_alpha[tid];
        float m = v;
#pragma unroll
        for (int o = 8; o; o >>= 1) m = fmaxf(m, __shfl_xor_sync(0xffffffffu, m, o));
        float e = __expf(v - m);
        float sm = e;
#pragma unroll
        for (int o = 8; o; o >>= 1) sm += __shfl_xor_sync(0xffffffffu, sm, o);
        s_wgt[tid] = e / sm;
    }
    __syncthreads();

    // ---- phase E: attn_res ----
    {
        int h = tid >> 5, hd = tid & 31;
        const __nv_bfloat16* hs = (const __nv_bfloat16*)s_hsampb;
        float res = 0.f;
#pragma unroll
        for (int lp = 0; lp < 16; lp++)
            res = fmaf(s_wgt[(h << 4) + lp],
                       __bfloat162float(hs[((h << 4) + lp)*34 + hd]), res);
        g_xh[n*1024 + 256 + tid] = res;
    }
}

// ------------------------- batched in-place log-softmax -------------------------
__global__ __launch_bounds__(256)
void logsoftmax_inplace(float* __restrict__ out)
{
    __shared__ float sm_m[8], sm_s[8];
    const int r = blockIdx.x;           // 0..5119
    const int q = r & 255, st = r >> 8;
    float* row = out + ((size_t)q * NSTEP + st) * VVn;
    const float4* row4 = (const float4*)row;
    const int tid = threadIdx.x;

    float m = -1e30f, s = 0.f;
    for (int v = tid; v < VVn/4; v += 256) {
        float4 x = row4[v];
        float xm = fmaxf(fmaxf(x.x, x.y), fmaxf(x.z, x.w));
        if (xm > m) { s *= __expf(m - xm); m = xm; }
        s += __expf(x.x - m) + __expf(x.y - m) + __expf(x.z - m) + __expf(x.w - m);
    }
#pragma unroll
    for (int o = 16; o; o >>= 1) {
        float mo = __shfl_xor_sync(0xffffffffu, m, o);
        float so = __shfl_xor_sync(0xffffffffu, s, o);
        float mn = fmaxf(m, mo);
        s = s * __expf(m - mn) + so * __expf(mo - mn);
        m = mn;
    }
    if ((tid & 31) == 0) { sm_m[tid >> 5] = m; sm_s[tid >> 5] = s; }
    __syncthreads();
    float mm = -1e30f, ss = 0.f;
#pragma unroll
    for (int i = 0; i < 8; i++) {
        float mi = sm_m[i], si = sm_s[i];
        float mn = fmaxf(mm, mi);
        ss = ss * __expf(mm - mn) + si * __expf(mi - mn);
        mm = mn;
    }
    float lse = mm + logf(ss);

    float4* op = (float4*)row;
    for (int v = tid; v < VVn/4; v += 256) {
        float4 x = row4[v];
        op[v] = make_float4(x.x - lse, x.y - lse, x.z - lse, x.w - lse);
    }
}

// ------------------------- launch -------------------------
extern "C" void kernel_launch(void* const* d_in, const int* in_sizes, int n_in,
                              void* d_out, int out_size)
{
    const int*   seq    = (const int*)  d_in[0];
    const float* query  = (const float*)d_in[1];
    const float* rp     = (const float*)d_in[2];
    const float* enc    = (const float*)d_in[3];
    const float* mask   = (const float*)d_in[4];
    const float* vrr    = (const float*)d_in[5];
    const float* embw   = (const float*)d_in[6];
    const float* logitw = (const float*)d_in[7];
    const float* logitb = (const float*)d_in[8];
    const float* valuew = (const float*)d_in[9];
    const float* valueb = (const float*)d_in[10];
    const float* offw   = (const float*)d_in[11];
    const float* offb   = (const float*)d_in[12];
    const float* aww    = (const float*)d_in[13];
    const float* awb    = (const float*)d_in[14];
    const float* ctxw   = (const float*)d_in[15];
    const float* ctxb   = (const float*)d_in[16];
    const float* hsw    = (const float*)d_in[17];
    const float* hsb    = (const float*)d_in[18];
    const float* alphaw = (const float*)d_in[19];
    const float* alphab = (const float*)d_in[20];
    const float* wih    = (const float*)d_in[21];
    const float* whh    = (const float*)d_in[22];
    float* out = (float*)d_out;

    float *p_mixp, *p_hq, *p_xh, *p_hseq;
    __nv_bfloat16 *p_bigwt, *p_gatewt, *p_logitwt, *p_valuewt;
    cudaGetSymbolAddress((void**)&p_mixp,    g_mixp);
    cudaGetSymbolAddress((void**)&p_hq,      g_hq);
    cudaGetSymbolAddress((void**)&p_xh,      g_xh);
    cudaGetSymbolAddress((void**)&p_hseq,    g_hseq);
    cudaGetSymbolAddress((void**)&p_bigwt,   g_bigwt);
    cudaGetSymbolAddress((void**)&p_gatewt,  g_gatewt);
    cudaGetSymbolAddress((void**)&p_logitwt, g_logitwt);
    cudaGetSymbolAddress((void**)&p_valuewt, g_valuewt);

    const int SMEM_MMA = 33792 + 2*128*36*4;   // 70656
    cudaFuncSetAttribute(gemm_mma<0>, cudaFuncAttributeMaxDynamicSharedMemorySize, SMEM_MMA);
    cudaFuncSetAttribute(gemm_mma<1>, cudaFuncAttributeMaxDynamicSharedMemorySize, SMEM_MMA);
    cudaFuncSetAttribute(gemm_mma<2>, cudaFuncAttributeMaxDynamicSharedMemorySize, SMEM_MMA);
    cudaFuncSetAttribute(gemm_mma<3>, cudaFuncAttributeMaxDynamicSharedMemorySize, SMEM_MMA);

    // preamble
    build_bigwt  <<<1024, 256>>>(offw, aww, hsw, offb, awb, hsb);
    build_gatewt <<<4096, 256>>>(wih, whh);
    build_logitwt<<<VPAD, 256>>>(logitw);
    build_misc   <<<256, 256>>>(ctxw, valuew);
    init_state   <<<NEq, 256>>>(query);
    // value = (enc @ value_w + b) * mask -> g_value[b][h][t][hd]
    gemm_mma<1><<<dim3(2, NB*TTn/64, 1), 256, SMEM_MMA>>>(
        enc, DDim, p_valuewt, 256, valueb, nullptr, 256, 256, 0, mask, 0);

    for (int step = 0; step < NSTEP; step++) {
        // mix = [h|query](256x512) @ bigw(512x512), split-K 4x128
        gemm_mma<0><<<dim3(4, 4, 4), 256, SMEM_MMA>>>(
            p_hq, 512, p_bigwt, 512, nullptr, p_mixp, 512, 128, NEq*512, nullptr, 0);
        msda_step<<<NEq, 256>>>(rp, vrr, seq, embw, ctxb, alphaw, alphab, step);
        // gates(gate-interleaved) + fused LSTM, full K=1024
        gemm_mma<2><<<dim3(8, 4, 1), 256, SMEM_MMA>>>(
            p_xh, 1024, p_gatewt, 1024, nullptr, nullptr, 1024, 1024, 0, nullptr, step);
    }

    // batched logits for all steps -> out (raw), then in-place log-softmax
    gemm_mma<3><<<dim3(VPAD/128, MTOT/64, 1), 256, SMEM_MMA>>>(
        p_hseq, DDim, p_logitwt, 256, logitb, out, VVn, 256, 0, nullptr, 0);
    logsoftmax_inplace<<<MTOT, 256>>>(out);
}

// round 5
// speedup vs baseline: 1.4592x; 1.4592x over previous
#include <cuda_runtime.h>
#include <cuda_bf16.h>
#include <math.h>
#include <stdint.h>

#define NB    8
#define NEq   256
#define SSq   21
#define NSTEP 20
#define DDim  256
#define HHn   8
#define HDn   32
#define VVn   10000
#define TTn   1920
#define VPAD  10112
#define MTOT  (NSTEP*NEq)   // 5120
#define LOOPBLK 128
#define SMEMSZ  70656       // 33792 (A) + 36864 (B x2)

// ------------------------- device scratch -------------------------
__device__ __align__(16) float g_value [NB*HHn*TTn*HDn];
__device__ __align__(16) float g_mixp  [4*NEq*512];
__device__ __align__(16) float g_gatesp[4*NEq*1024];
__device__ __align__(16) float g_hq    [NEq*512];          // [h | query]
__device__ __align__(16) float g_xh    [NEq*1024];         // [emb | attn | query | h]
__device__ __align__(16) float g_hseq  [MTOT*DDim];        // h2 per step (row = st*256+q)
__device__ __align__(16) float g_c     [NEq*DDim];
__device__ __align__(16) float g_bigb  [512];
__device__ __align__(16) __nv_bfloat16 g_bigwt  [512*512];     // [n][k]
__device__ __align__(16) __nv_bfloat16 g_gatewt [1024*1024];   // gate-interleaved [n=4d+g][k]
__device__ __align__(16) __nv_bfloat16 g_logitwt[VPAD*256];    // [n][k]
__device__ __align__(16) __nv_bfloat16 g_ctxwt  [256*32];      // [n][k]
__device__ __align__(16) __nv_bfloat16 g_valuewt[256*256];     // [n][k]

__device__ unsigned g_bar_cnt;
__device__ volatile unsigned g_bar_gen;

// ------------------------- helpers -------------------------
__device__ __forceinline__ float tanha(float x) {
    float y; asm("tanh.approx.f32 %0, %1;" : "=f"(y) : "f"(x)); return y;
}
__device__ __forceinline__ void mma16816(float* c, const uint32_t* a, const uint32_t* b) {
    asm volatile(
        "mma.sync.aligned.m16n8k16.row.col.f32.bf16.bf16.f32 "
        "{%0,%1,%2,%3}, {%4,%5,%6,%7}, {%8,%9}, {%0,%1,%2,%3};"
        : "+f"(c[0]), "+f"(c[1]), "+f"(c[2]), "+f"(c[3])
        : "r"(a[0]), "r"(a[1]), "r"(a[2]), "r"(a[3]), "r"(b[0]), "r"(b[1]));
}
__device__ __forceinline__ void cpasync16(uint32_t dst, const void* src) {
    asm volatile("cp.async.cg.shared.global [%0], [%1], 16;" :: "r"(dst), "l"(src));
}

// software grid barrier (generation-based; replay-safe)
__device__ __forceinline__ void gridbar() {
    __syncthreads();
    if (threadIdx.x == 0) {
        __threadfence();
        unsigned gen = g_bar_gen;
        if (atomicAdd(&g_bar_cnt, 1u) == (unsigned)(LOOPBLK - 1)) {
            g_bar_cnt = 0;
            __threadfence();
            g_bar_gen = gen + 1;
        } else {
            while (g_bar_gen == gen) { }
            __threadfence();
        }
    }
    __syncthreads();
}

// ------------------------- GEMM mainloop (64x128 tile, 8 warps) -------------------------
template<int KCHUNK>
__device__ __forceinline__ void gemm_core(
    const float* __restrict__ A, int lda,
    const __nv_bfloat16* __restrict__ Wt, int ldw,
    int n0, int row0, int kbeg, char* smem, float acc[2][4][4])
{
    uint32_t* Asw = (uint32_t*)smem;                 // [64][132] words
    uint32_t* Bsw = (uint32_t*)(smem + 33792);       // [2][128][36] words
    const int SAW = 132;
    const int NKT = KCHUNK >> 4;

    const int tid  = threadIdx.x;
    const int lane = tid & 31, warp = tid >> 5;
    const int wm = warp >> 2, wn = warp & 3;
    const int g = lane >> 2, t = lane & 3;
    const int bn = tid >> 1, bq = (tid & 1) << 3;
    const uint32_t bsm = (uint32_t)__cvta_generic_to_shared(Bsw);

    cpasync16(bsm + (uint32_t)((bn*36 + (bq>>1))*4),
              Wt + (size_t)(n0 + bn) * ldw + kbeg + bq);
    asm volatile("cp.async.commit_group;");

#pragma unroll
    for (int i = 0; i < 2; i++)
#pragma unroll
        for (int j = 0; j < 4; j++)
#pragma unroll
            for (int q = 0; q < 4; q++) acc[i][j][q] = 0.f;

#pragma unroll 1
    for (int ksg = 0; ksg < NKT; ksg++) {
        __syncthreads();
        if (ksg == 0) {
#pragma unroll
            for (int idx = tid * 4; idx < 64 * KCHUNK; idx += 1024) {
                int r = idx / KCHUNK, cc = idx % KCHUNK;
                float4 v = *(const float4*)(A + (size_t)(row0 + r) * lda + kbeg + cc);
                __nv_bfloat162 p0 = __float22bfloat162_rn(make_float2(v.x, v.y));
                __nv_bfloat162 p1 = __float22bfloat162_rn(make_float2(v.z, v.w));
                Asw[r * SAW + (cc >> 1)]     = *(uint32_t*)&p0;
                Asw[r * SAW + (cc >> 1) + 1] = *(uint32_t*)&p1;
            }
        }
        if (ksg + 1 < NKT)
            cpasync16(bsm + (uint32_t)(((((ksg+1)&1)*128*36) + bn*36 + (bq>>1))*4),
                      Wt + (size_t)(n0 + bn) * ldw + kbeg + (ksg + 1) * 16 + bq);
        asm volatile("cp.async.commit_group;");
        asm volatile("cp.async.wait_group 1;");
        __syncthreads();

        const int wo = ksg * 8;
        uint32_t a[2][4];
#pragma unroll
        for (int mt = 0; mt < 2; mt++) {
            const uint32_t* ap = Asw + (wm*32 + mt*16 + g) * SAW + wo + t;
            a[mt][0] = ap[0];
            a[mt][1] = ap[8 * SAW];
            a[mt][2] = ap[4];
            a[mt][3] = ap[8 * SAW + 4];
        }
        const uint32_t* bbase = Bsw + (ksg & 1) * 128 * 36;
        uint32_t bf[4][2];
#pragma unroll
        for (int nt = 0; nt < 4; nt++) {
            const uint32_t* bp = bbase + (wn*32 + nt*8 + g) * 36 + t;
            bf[nt][0] = bp[0];
            bf[nt][1] = bp[4];
        }
#pragma unroll
        for (int mt = 0; mt < 2; mt++)
#pragma unroll
            for (int nt = 0; nt < 4; nt++)
                mma16816(acc[mt][nt], a[mt], bf[nt]);
    }
}

__device__ __forceinline__ void epi_partials(float acc[2][4][4], float* C, int N,
                                             int n0, int row0, size_t zoff)
{
    const int lane = threadIdx.x & 31, warp = threadIdx.x >> 5;
    const int wm = warp >> 2, wn = warp & 3;
    const int g = lane >> 2, t = lane & 3;
#pragma unroll
    for (int mt = 0; mt < 2; mt++) {
        int m = row0 + wm*32 + mt*16 + g;
#pragma unroll
        for (int nt = 0; nt < 4; nt++) {
            int n = n0 + wn*32 + nt*8 + (t << 1);
            float* c = acc[mt][nt];
            *(float2*)(C + zoff + (size_t)m * N + n)       = make_float2(c[0], c[1]);
            *(float2*)(C + zoff + (size_t)(m + 8) * N + n) = make_float2(c[2], c[3]);
        }
    }
}

// ------------------------- standalone GEMM kernels -------------------------
// value = (enc @ value_w + b) * mask -> g_value[b][h][t][hd]
__global__ __launch_bounds__(256)
void value_kernel(const float* __restrict__ enc, const float* __restrict__ valueb,
                  const float* __restrict__ mask)
{
    extern __shared__ char smem[];
    float acc[2][4][4];
    const int n0 = blockIdx.x * 128, row0 = blockIdx.y * 64;
    gemm_core<256>(enc, 256, g_valuewt, 256, n0, row0, 0, smem, acc);

    const int lane = threadIdx.x & 31, warp = threadIdx.x >> 5;
    const int wm = warp >> 2, wn = warp & 3;
    const int g = lane >> 2, t = lane & 3;
#pragma unroll
    for (int mt = 0; mt < 2; mt++) {
#pragma unroll
        for (int mi = 0; mi < 2; mi++) {
            int m  = row0 + wm*32 + mt*16 + g + mi*8;
            int b  = m / TTn;
            int tt = m - b * TTn;
            float mk = mask[m];
#pragma unroll
            for (int nt = 0; nt < 4; nt++) {
                int n = n0 + wn*32 + nt*8 + (t << 1);
                int h = n >> 5, hd = n & 31;
                float* c = acc[mt][nt];
                float v0 = (c[mi*2]   + valueb[n])     * mk;
                float v1 = (c[mi*2+1] + valueb[n + 1]) * mk;
                *(float2*)(g_value + (((size_t)(b*HHn + h))*TTn + tt)*HDn + hd)
                    = make_float2(v0, v1);
            }
        }
    }
}

// logits = hseq @ logit_w + b -> scattered into out[(q*NSTEP+st)*VVn + n]
__global__ __launch_bounds__(256)
void logits_kernel(const float* __restrict__ logitb, float* __restrict__ out)
{
    extern __shared__ char smem[];
    float acc[2][4][4];
    const int n0 = blockIdx.x * 128, row0 = blockIdx.y * 64;
    gemm_core<256>(g_hseq, 256, g_logitwt, 256, n0, row0, 0, smem, acc);

    const int lane = threadIdx.x & 31, warp = threadIdx.x >> 5;
    const int wm = warp >> 2, wn = warp & 3;
    const int g = lane >> 2, t = lane & 3;
#pragma unroll
    for (int mt = 0; mt < 2; mt++) {
#pragma unroll
        for (int mi = 0; mi < 2; mi++) {
            int m  = row0 + wm*32 + mt*16 + g + mi*8;
            int q  = m & 255, st = m >> 8;
            float* orow = out + ((size_t)q * NSTEP + st) * VVn;
#pragma unroll
            for (int nt = 0; nt < 4; nt++) {
                int n = n0 + wn*32 + nt*8 + (t << 1);
                if (n < VVn) {
                    float* c = acc[mt][nt];
                    *(float2*)(orow + n) = make_float2(c[mi*2]   + logitb[n],
                                                       c[mi*2+1] + logitb[n+1]);
                }
            }
        }
    }
}

// ------------------------- preamble kernels -------------------------
__global__ void build_bigwt(const float* __restrict__ offw, const float* __restrict__ aww,
                            const float* __restrict__ hsw,  const float* __restrict__ offb,
                            const float* __restrict__ awb,  const float* __restrict__ hsb)
{
    int i = blockIdx.x * 256 + threadIdx.x;
    int n = i >> 9, k = i & 511;
    float v;
    if (n < 128)      v = offw[k*128 + n];
    else if (n < 256) v = aww[k*128 + (n - 128)];
    else              v = (k < 256) ? hsw[k*256 + (n - 256)] : 0.f;
    g_bigwt[i] = __float2bfloat16(v);
    if (i < 512)
        g_bigb[i] = (i < 128) ? offb[i] : (i < 256) ? awb[i-128] : hsb[i-256];
}

__global__ void build_gatewt(const float* __restrict__ wih, const float* __restrict__ whh)
{
    int i = blockIdx.x * 256 + threadIdx.x;
    int n = i >> 10, k = i & 1023;
    int d = n >> 2, gate = n & 3;
    int j = gate * 256 + d;
    float v = (k < 768) ? wih[k*1024 + j] : whh[(k - 768)*1024 + j];
    g_gatewt[i] = __float2bfloat16(v);
}

__global__ void build_logitwt(const float* __restrict__ lw)
{
    int i = blockIdx.x * 256 + threadIdx.x;
    int k = i / VPAD, n = i - k * VPAD;
    float v = (n < VVn) ? lw[(size_t)k * VVn + n] : 0.f;
    g_logitwt[(size_t)n * 256 + k] = __float2bfloat16(v);
}

__global__ void build_misc(const float* __restrict__ ctxw, const float* __restrict__ valuew)
{
    int i = blockIdx.x * 256 + threadIdx.x;
    if (i < 256*32) {
        int n = i >> 5, k = i & 31;
        g_ctxwt[n*32 + k] = __float2bfloat16(ctxw[k*256 + n]);
    }
    int n = i >> 8, k = i & 255;
    g_valuewt[n*256 + k] = __float2bfloat16(valuew[k*256 + n]);
}

__global__ void init_state(const float* __restrict__ query)
{
    int n = blockIdx.x, d = threadIdx.x;
    float q = query[n*DDim + d];
    g_c[n*DDim + d] = 0.f;
    g_hq[n*512 + d]        = 0.f;
    g_hq[n*512 + 256 + d]  = q;
    g_xh[n*1024 + 512 + d] = q;
    g_xh[n*1024 + 768 + d] = 0.f;
}

// ------------------------- fused MSDA (one query) -------------------------
__device__ void msda_one(int n, int step,
                         const float* __restrict__ rp,   const float* __restrict__ vr,
                         const int*   __restrict__ seq,  const float* __restrict__ embw,
                         const float* __restrict__ ctxb, const float* __restrict__ alphaw,
                         const float* __restrict__ alphab, char* smem, bool loadctx)
{
    uint32_t* s_hsampb = (uint32_t*)smem;            // [128][17] words (bf16 pairs)
    uint32_t* s_ctx    = (uint32_t*)(smem + 8704);   // [256][17] words
    float* s_hb    = (float*)(smem + 26112);
    float* s_aww   = (float*)(smem + 27136);
    float* s_off   = (float*)(smem + 28160);
    float* s_aw    = (float*)(smem + 28672);
    float* s_alpha = (float*)(smem + 29184);
    float* s_wgt   = (float*)(smem + 29696);

    const int b    = n >> 5;
    const int tid  = threadIdx.x;
    const int lane = tid & 31;
    const int w    = tid >> 5;

    __syncthreads();

    // ---- phase A ----
    {
        int tok = (step == 0) ? 1 : seq[n*SSq + step - 1];
        g_xh[n*1024 + tid] = embw[(size_t)tok * DDim + tid];
    }
    {
        float s = 0.f;
#pragma unroll
        for (int z = 0; z < 4; z++) s += g_mixp[z*(NEq*512) + n*512 + 256 + tid];
        s_hb[tid] = s + g_bigb[256 + tid] + ctxb[tid];
        s_aww[tid] = alphaw[tid];
    }
    if (loadctx) {
        const uint32_t* cg = (const uint32_t*)g_ctxwt;
        for (int i = tid; i < 256*16; i += 256)
            s_ctx[(i >> 4)*17 + (i & 15)] = cg[i];
    }
    if (tid < 128) {
        float so = 0.f, sa = 0.f;
#pragma unroll
        for (int z = 0; z < 4; z++) {
            so += g_mixp[z*(NEq*512) + n*512 + tid];
            sa += g_mixp[z*(NEq*512) + n*512 + 128 + tid];
        }
        so += g_bigb[tid];
        sa += g_bigb[128 + tid];
        s_off[tid] = so;
        float m = sa;
#pragma unroll
        for (int o = 8; o; o >>= 1) m = fmaxf(m, __shfl_xor_sync(0xffffffffu, m, o));
        float e = __expf(sa - m);
        float sm = e;
#pragma unroll
        for (int o = 8; o; o >>= 1) sm += __shfl_xor_sync(0xffffffffu, sm, o);
        s_aw[tid] = e / sm;
    }
    __syncthreads();

    // ---- phase B: bilinear sampling -> bf16 smem ----
    {
        const float rpn = rp[n];
        __nv_bfloat16* hs = (__nv_bfloat16*)s_hsampb;
#pragma unroll
        for (int i = 0; i < 16; i++) {
            int r = (w << 4) + i;
            int h = r >> 4;
            int l = (r >> 2) & 3;
            int shape_l = 1024 >> l;
            int start_l = 2048 - (2048 >> l);
            float refl = rpn * vr[b*4 + l];
            float x = refl * (float)shape_l + s_off[r] - 0.5f;
            float x0f = floorf(x);
            float wf = x - x0f;
            int x0 = (int)x0f;
            const float* vbase = g_value + (((size_t)(b*HHn + h))*TTn + start_l) * HDn;
            float g0 = (x0 >= 0     && x0     < shape_l) ? vbase[(size_t)x0     * HDn + lane] : 0.f;
            float g1 = (x0 + 1 >= 0 && x0 + 1 < shape_l) ? vbase[(size_t)(x0+1) * HDn + lane] : 0.f;
            hs[r*34 + lane] = __float2bfloat16((g0 * (1.f - wf) + g1 * wf) * s_aw[r]);
        }
    }
    __syncthreads();

    // ---- phase C: alpha via tensor cores ----
    {
        const int g = lane >> 2, t = lane & 3;
        const int r0 = w << 4;
        const float ab = alphab[0];

        uint32_t a[2][4];
#pragma unroll
        for (int ks = 0; ks < 2; ks++) {
            const uint32_t* ap = s_hsampb + (r0 + g) * 17 + ks*8 + t;
            a[ks][0] = ap[0];
            a[ks][1] = ap[8 * 17];
            a[ks][2] = ap[4];
            a[ks][3] = ap[8 * 17 + 4];
        }
        float p0 = 0.f, p1 = 0.f;
#pragma unroll
        for (int nb = 0; nb < 256; nb += 8) {
            float c[4] = {0.f, 0.f, 0.f, 0.f};
#pragma unroll
            for (int ks = 0; ks < 2; ks++) {
                const uint32_t* bp = s_ctx + (nb + g) * 17 + ks*8 + t;
                uint32_t bf2[2] = { bp[0], bp[4] };
                mma16816(c, a[ks], bf2);
            }
            int col = nb + (t << 1);
            float hb0 = s_hb[col], hb1 = s_hb[col + 1];
            float aw0 = s_aww[col], aw1 = s_aww[col + 1];
            p0 = fmaf(tanha(c[0] + hb0), aw0, fmaf(tanha(c[1] + hb1), aw1, p0));
            p1 = fmaf(tanha(c[2] + hb0), aw0, fmaf(tanha(c[3] + hb1), aw1, p1));
        }
        p0 += __shfl_xor_sync(0xffffffffu, p0, 1);
        p0 += __shfl_xor_sync(0xffffffffu, p0, 2);
        p1 += __shfl_xor_sync(0xffffffffu, p1, 1);
        p1 += __shfl_xor_sync(0xffffffffu, p1, 2);
        if (t == 0) {
            s_alpha[r0 + g]     = p0 + ab;
            s_alpha[r0 + g + 8] = p1 + ab;
        }
    }
    __syncthreads();

    // ---- phase D: softmax over 16 per head ----
    if (tid < 128) {
        float v = s_alpha[tid];
        float m = v;
#pragma unroll
        for (int o = 8; o; o >>= 1) m = fmaxf(m, __shfl_xor_sync(0xffffffffu, m, o));
        float e = __expf(v - m);
        float sm = e;
#pragma unroll
        for (int o = 8; o; o >>= 1) sm += __shfl_xor_sync(0xffffffffu, sm, o);
        s_wgt[tid] = e / sm;
    }
    __syncthreads();

    // ---- phase E: attn_res ----
    {
        int h = tid >> 5, hd = tid & 31;
        const __nv_bfloat16* hs = (const __nv_bfloat16*)s_hsampb;
        float res = 0.f;
#pragma unroll
        for (int lp = 0; lp < 16; lp++)
            res = fmaf(s_wgt[(h << 4) + lp],
                       __bfloat162float(hs[((h << 4) + lp)*34 + hd]), res);
        g_xh[n*1024 + 256 + tid] = res;
    }
    __syncthreads();
}

// ------------------------- persistent recurrent loop -------------------------
__global__ __launch_bounds__(256)
void loop_kernel(const float* __restrict__ rp,   const float* __restrict__ vr,
                 const int*   __restrict__ seq,  const float* __restrict__ embw,
                 const float* __restrict__ ctxb, const float* __restrict__ alphaw,
                 const float* __restrict__ alphab)
{
    extern __shared__ char smem[];
    const int blk = blockIdx.x;
    const int tid = threadIdx.x;

    for (int it = 0; it <= NSTEP; it++) {
        if (it > 0) {
            // ---- P0: LSTM update for 2 queries (reads gates partials of step it-1) ----
#pragma unroll
            for (int j = 0; j < 2; j++) {
                int q = blk*2 + j;
                int d = tid;
                float4 s = make_float4(0.f, 0.f, 0.f, 0.f);
#pragma unroll
                for (int z = 0; z < 4; z++) {
                    float4 gp = *(const float4*)&g_gatesp[(size_t)z*NEq*1024 + q*1024 + d*4];
                    s.x += gp.x; s.y += gp.y; s.z += gp.z; s.w += gp.w;
                }
                float c  = g_c[q*DDim + d];
                float si = 1.f / (1.f + expf(-s.x));
                float sf = 1.f / (1.f + expf(-s.y));
                float so = 1.f / (1.f + expf(-s.w));
                float c2 = sf * c + si * tanhf(s.z);
                float h2 = so * tanhf(c2);
                g_c[q*DDim + d]        = c2;
                g_hq[q*512 + d]        = h2;
                g_xh[q*1024 + 768 + d] = h2;
                g_hseq[((size_t)(it-1)*NEq + q)*DDim + d] = h2;
            }
            if (it == NSTEP) break;
            gridbar();
        }

        // ---- P1: mix GEMM (256x512 @ 512x512), split-K4, blocks 0..63 ----
        if (blk < 64) {
            int bz = blk >> 4, by = (blk >> 2) & 3, bx = blk & 3;
            float acc[2][4][4];
            gemm_core<128>(g_hq, 512, g_bigwt, 512, bx*128, by*64, bz*128, smem, acc);
            epi_partials(acc, g_mixp, 512, bx*128, by*64, (size_t)bz*NEq*512);
        }
        gridbar();

        // ---- P2: MSDA, 2 queries per block ----
        msda_one(blk*2,     it, rp, vr, seq, embw, ctxb, alphaw, alphab, smem, true);
        msda_one(blk*2 + 1, it, rp, vr, seq, embw, ctxb, alphaw, alphab, smem, false);
        gridbar();

        // ---- P3: gates GEMM (256x1024 @ 1024x1024, gate-interleaved), split-K4 ----
        {
            int bz = blk >> 5, by = (blk >> 3) & 3, bx = blk & 7;
            float acc[2][4][4];
            gemm_core<256>(g_xh, 1024, g_gatewt, 1024, bx*128, by*64, bz*256, smem, acc);
            epi_partials(acc, g_gatesp, 1024, bx*128, by*64, (size_t)bz*NEq*1024);
        }
        gridbar();
    }
}

// ------------------------- batched in-place log-softmax -------------------------
__global__ __launch_bounds__(256)
void logsoftmax_inplace(float* __restrict__ out)
{
    __shared__ float sm_m[8], sm_s[8];
    const int r = blockIdx.x;
    const int q = r & 255, st = r >> 8;
    float* row = out + ((size_t)q * NSTEP + st) * VVn;
    const float4* row4 = (const float4*)row;
    const int tid = threadIdx.x;

    float m = -1e30f, s = 0.f;
    for (int v = tid; v < VVn/4; v += 256) {
        float4 x = row4[v];
        float xm = fmaxf(fmaxf(x.x, x.y), fmaxf(x.z, x.w));
        if (xm > m) { s *= __expf(m - xm); m = xm; }
        s += __expf(x.x - m) + __expf(x.y - m) + __expf(x.z - m) + __expf(x.w - m);
    }
#pragma unroll
    for (int o = 16; o; o >>= 1) {
        float mo = __shfl_xor_sync(0xffffffffu, m, o);
        float so = __shfl_xor_sync(0xffffffffu, s, o);
        float mn = fmaxf(m, mo);
        s = s * __expf(m - mn) + so * __expf(mo - mn);
        m = mn;
    }
    if ((tid & 31) == 0) { sm_m[tid >> 5] = m; sm_s[tid >> 5] = s; }
    __syncthreads();
    float mm = -1e30f, ss = 0.f;
#pragma unroll
    for (int i = 0; i < 8; i++) {
        float mi = sm_m[i], si = sm_s[i];
        float mn = fmaxf(mm, mi);
        ss = ss * __expf(mm - mn) + si * __expf(mi - mn);
        mm = mn;
    }
    float lse = mm + logf(ss);

    float4* op = (float4*)row;
    for (int v = tid; v < VVn/4; v += 256) {
        float4 x = row4[v];
        op[v] = make_float4(x.x - lse, x.y - lse, x.z - lse, x.w - lse);
    }
}

// ------------------------- launch -------------------------
extern "C" void kernel_launch(void* const* d_in, const int* in_sizes, int n_in,
                              void* d_out, int out_size)
{
    const int*   seq    = (const int*)  d_in[0];
    const float* query  = (const float*)d_in[1];
    const float* rp     = (const float*)d_in[2];
    const float* enc    = (const float*)d_in[3];
    const float* mask   = (const float*)d_in[4];
    const float* vrr    = (const float*)d_in[5];
    const float* embw   = (const float*)d_in[6];
    const float* logitw = (const float*)d_in[7];
    const float* logitb = (const float*)d_in[8];
    const float* valuew = (const float*)d_in[9];
    const float* valueb = (const float*)d_in[10];
    const float* offw   = (const float*)d_in[11];
    const float* offb   = (const float*)d_in[12];
    const float* aww    = (const float*)d_in[13];
    const float* awb    = (const float*)d_in[14];
    const float* ctxw   = (const float*)d_in[15];
    const float* ctxb   = (const float*)d_in[16];
    const float* hsw    = (const float*)d_in[17];
    const float* hsb    = (const float*)d_in[18];
    const float* alphaw = (const float*)d_in[19];
    const float* alphab = (const float*)d_in[20];
    const float* wih    = (const float*)d_in[21];
    const float* whh    = (const float*)d_in[22];
    float* out = (float*)d_out;

    cudaFuncSetAttribute(value_kernel,  cudaFuncAttributeMaxDynamicSharedMemorySize, SMEMSZ);
    cudaFuncSetAttribute(logits_kernel, cudaFuncAttributeMaxDynamicSharedMemorySize, SMEMSZ);
    cudaFuncSetAttribute(loop_kernel,   cudaFuncAttributeMaxDynamicSharedMemorySize, SMEMSZ);

    // preamble (one-time weight transforms + state init)
    build_bigwt  <<<1024, 256>>>(offw, aww, hsw, offb, awb, hsb);
    build_gatewt <<<4096, 256>>>(wih, whh);
    build_logitwt<<<VPAD, 256>>>(logitw);
    build_misc   <<<256, 256>>>(ctxw, valuew);
    init_state   <<<NEq, 256>>>(query);

    // value projection
    value_kernel<<<dim3(2, NB*TTn/64), 256, SMEMSZ>>>(enc, valueb, mask);

    // whole 20-step recurrence in one persistent kernel
    loop_kernel<<<LOOPBLK, 256, SMEMSZ>>>(rp, vrr, seq, embw, ctxb, alphaw, alphab);

    // batched logits + log-softmax
    logits_kernel<<<dim3(VPAD/128, MTOT/64), 256, SMEMSZ>>>(logitb, out);
    logsoftmax_inplace<<<MTOT, 256>>>(out);
}